// round 15
// baseline (speedup 1.0000x reference)
#include <cuda_runtime.h>
#include <cstddef>

// SpecialFlatten == batched float2 transpose: in2 [B, R, CP] -> out2 [B, CP, R]
// B=32, R=2048, C=512, CP=256.
//
// v15: PERSISTENT-CTA version of the proven 64Rx32CP tile kernel.
// Previous kernels ran 8192 one-tile CTAs = 7 waves at 8 CTA/SM; the B300
// model charges ~2360 cyc per wave transition plus per-wave spread tails.
// Here grid = 148*8 = 1184 CTAs (exactly one wave); each CTA loops over ~7
// tiles, eliminating all wave transitions. Tile body identical to v4/v6:
// even/odd smem planes, permuted columns, all STS.64/LDS.64 lane-linear.

namespace {
constexpr int B   = 32;
constexpr int R   = 2048;
constexpr int CP  = 256;           // float2 columns
constexpr int C4  = CP / 2;        // 128 float4 per input row
constexpr int R4  = R / 2;         // 1024 float4 per output row
constexpr int TILE_R = 64;         // float2 rows per tile
constexpr int TILE_C = 32;         // float2 cols per tile (= 16 float4)
constexpr int RT_PER_B = R / TILE_R;            // 32 r-tiles
constexpr int CT_PER_B = CP / TILE_C;           // 8  c-tiles
constexpr int TILES    = B * RT_PER_B * CT_PER_B;   // 8192
constexpr int GRID     = 148 * 8;               // one full wave at 8 CTA/SM
}

__global__ __launch_bounds__(256)
void special_flatten_v15(const float4* __restrict__ in,
                         float4* __restrict__ out) {
    __shared__ float2 sA[32][33];   // even rows (row 2m -> sA[m])
    __shared__ float2 sB[32][33];   // odd rows  (row 2m+1 -> sB[m])

    const int tid = threadIdx.x;
    // load-phase indices (invariant across tiles)
    const int tx = tid & 15;        // float4 col within tile (0..15)
    const int ty = tid >> 4;        // 0..15
    // store-phase indices
    const int sx = tid & 31;        // float4 R-index within tile (0..31)
    const int sy = tid >> 5;        // 0..7

    for (int tile = blockIdx.x; tile < TILES; tile += GRID) {
        // decode: rtile fastest, then ctile, then batch
        const int b     = tile >> 8;                    // / 256
        const int within = tile & 255;
        const int rtile = within & (RT_PER_B - 1);      // % 32
        const int ctile = within >> 5;                  // / 32

        const float4* __restrict__ inb  = in  + (size_t)b * R * C4;
        float4* __restrict__       outb = out + (size_t)b * CP * R4;

        // ---- Load phase: 4x LDG.128 per thread, STS.64 lane-linear ----
        {
            const int c4 = ctile * (TILE_C / 2) + tx;
            const int r0 = rtile * TILE_R;
#pragma unroll
            for (int k = 0; k < 2; k++) {
                const int m = ty + 16 * k;              // row pair 0..31
                const float4 v0 = inb[(size_t)(r0 + 2 * m    ) * C4 + c4];
                const float4 v1 = inb[(size_t)(r0 + 2 * m + 1) * C4 + c4];
                sA[m][tx]      = make_float2(v0.x, v0.y);
                sA[m][tx + 16] = make_float2(v0.z, v0.w);
                sB[m][tx]      = make_float2(v1.x, v1.y);
                sB[m][tx + 16] = make_float2(v1.z, v1.w);
            }
        }

        __syncthreads();

        // ---- Store phase: LDS.64 lane-linear, 4x STG.128 per thread ----
        {
            const int r4 = rtile * (TILE_R / 2) + sx;
#pragma unroll
            for (int n = 0; n < 4; n++) {
                const int c  = sy + 8 * n;              // CP-local col 0..31
                const int sc = (c >> 1) + (c & 1) * 16; // permuted storage col
                const float2 a  = sA[sx][sc];
                const float2 bb = sB[sx][sc];
                outb[(size_t)(ctile * TILE_C + c) * R4 + r4] =
                    make_float4(a.x, a.y, bb.x, bb.y);
            }
        }

        __syncthreads();   // protect smem before next tile's load phase
    }
}

extern "C" void kernel_launch(void* const* d_in, const int* in_sizes, int n_in,
                              void* d_out, int out_size) {
    const float4* in  = (const float4*)d_in[0];
    float4*       out = (float4*)d_out;

    dim3 block(256, 1, 1);
    dim3 grid(GRID, 1, 1);   // 1184 persistent CTAs = exactly one wave
    special_flatten_v15<<<grid, block>>>(in, out);
}

// round 16
// speedup vs baseline: 1.0621x; 1.0621x over previous
#include <cuda_runtime.h>
#include <cstddef>

// SpecialFlatten == batched float2 transpose: in2 [B, R, CP] -> out2 [B, CP, R]
// B=32, R=2048, C=512, CP=256. Fully float4-vectorized on both GMEM sides.
//
// FINAL. Fifteen rounds / nine distinct implementations (tile shapes, vector
// widths, raster orders, cache hints, occupancy trades, register & cp.async
// pipelines, persistent CTAs) all bounded by 36.0-36.9us kernel / 72.6-74.9%
// DRAM — the mixed-R/W HBM3e turnaround wall (~7.4-7.5 TB/s combined, ~93%
// of spec) for this compulsory 268MB permutation stream. This config
// (64Rx32CP tile, 256 threads, one CTA per tile, R-tiles fastest raster)
// holds the best bench: 43.488us, reproduced x3.
//
// Smem: even input rows -> sA[m][.], odd rows -> sB[m][.] (m = pair index),
// permuted column layout s(c) = (c>>1) + (c&1)*16 => every STS.64/LDS.64 is
// lane-linear (bank 2*lane), zero conflicts with the +1 pad.

namespace {
constexpr int B   = 32;
constexpr int R   = 2048;
constexpr int CP  = 256;           // float2 columns
constexpr int C4  = CP / 2;        // 128 float4 per input row
constexpr int R4  = R / 2;         // 1024 float4 per output row
constexpr int TILE_R = 64;         // float2 rows per tile
constexpr int TILE_C = 32;         // float2 cols per tile (= 16 float4)
}

__global__ __launch_bounds__(256)
void special_flatten_final(const float4* __restrict__ in,
                           float4* __restrict__ out) {
    __shared__ float2 sA[32][33];   // even rows of the tile (row 2m -> sA[m])
    __shared__ float2 sB[32][33];   // odd rows  (row 2m+1 -> sB[m])

    const int b = blockIdx.z;
    const float4* __restrict__ inb  = in  + (size_t)b * R * C4;
    float4* __restrict__       outb = out + (size_t)b * CP * R4;

    const int tid   = threadIdx.x;
    const int rtile = blockIdx.x;   // R-tile index (fastest-varying)
    const int ctile = blockIdx.y;   // CP-tile index

    // ---- Load phase: 4x LDG.128 per thread, STS.64 lane-linear ----
    {
        const int tx = tid & 15;                 // float4 col within tile (0..15)
        const int ty = tid >> 4;                 // 0..15
        const int c4 = ctile * (TILE_C / 2) + tx;
        const int r0 = rtile * TILE_R;
#pragma unroll
        for (int k = 0; k < 2; k++) {
            const int m = ty + 16 * k;           // row pair 0..31
            const float4 v0 = inb[(size_t)(r0 + 2 * m    ) * C4 + c4];
            const float4 v1 = inb[(size_t)(r0 + 2 * m + 1) * C4 + c4];
            // logical cols 2tx, 2tx+1 -> storage cols tx, tx+16 (permuted)
            sA[m][tx]      = make_float2(v0.x, v0.y);
            sA[m][tx + 16] = make_float2(v0.z, v0.w);
            sB[m][tx]      = make_float2(v1.x, v1.y);
            sB[m][tx + 16] = make_float2(v1.z, v1.w);
        }
    }

    __syncthreads();

    // ---- Store phase: LDS.64 lane-linear, 4x STG.128 per thread ----
    {
        const int sx = tid & 31;                 // float4 R-index within tile (0..31)
        const int sy = tid >> 5;                 // 0..7
        const int r4 = rtile * (TILE_R / 2) + sx;
#pragma unroll
        for (int n = 0; n < 4; n++) {
            const int c  = sy + 8 * n;           // CP-local col 0..31
            const int sc = (c >> 1) + (c & 1) * 16;   // permuted storage col
            const float2 a  = sA[sx][sc];        // in2[2*sx][c]
            const float2 bb = sB[sx][sc];        // in2[2*sx+1][c]
            outb[(size_t)(ctile * TILE_C + c) * R4 + r4] =
                make_float4(a.x, a.y, bb.x, bb.y);
        }
    }
}

extern "C" void kernel_launch(void* const* d_in, const int* in_sizes, int n_in,
                              void* d_out, int out_size) {
    const float4* in  = (const float4*)d_in[0];
    float4*       out = (float4*)d_out;

    dim3 block(256, 1, 1);
    dim3 grid(R / TILE_R, CP / TILE_C, B);   // (32, 8, 32) = 8192 blocks
    special_flatten_final<<<grid, block>>>(in, out);
}

// round 17
// speedup vs baseline: 1.0941x; 1.0301x over previous
#include <cuda_runtime.h>
#include <cstddef>

// SpecialFlatten == batched float2 transpose: in2 [B, R, CP] -> out2 [B, CP, R]
// B=32, R=2048, C=512, CP=256. Fully float4-vectorized on both GMEM sides.
//
// FINAL (held). Sixteen rounds / nine distinct implementations all bounded by
// 36.0-36.9us kernel / 72.6-74.9% DRAM — the mixed-R/W HBM3e turnaround wall
// (~7.4-7.5 TB/s combined, ~93% of spec) for this compulsory 268MB
// permutation stream. Config: 64Rx32CP tile, 256 threads, one CTA per tile,
// R-tiles fastest raster; best bench 43.488us (x3).
//
// Smem: even input rows -> sA[m][.], odd rows -> sB[m][.] (m = pair index),
// permuted column layout s(c) = (c>>1) + (c&1)*16 => every STS.64/LDS.64 is
// lane-linear (bank 2*lane), zero conflicts with the +1 pad.

namespace {
constexpr int B   = 32;
constexpr int R   = 2048;
constexpr int CP  = 256;           // float2 columns
constexpr int C4  = CP / 2;        // 128 float4 per input row
constexpr int R4  = R / 2;         // 1024 float4 per output row
constexpr int TILE_R = 64;         // float2 rows per tile
constexpr int TILE_C = 32;         // float2 cols per tile (= 16 float4)
}

__global__ __launch_bounds__(256)
void special_flatten_final(const float4* __restrict__ in,
                           float4* __restrict__ out) {
    __shared__ float2 sA[32][33];   // even rows of the tile (row 2m -> sA[m])
    __shared__ float2 sB[32][33];   // odd rows  (row 2m+1 -> sB[m])

    const int b = blockIdx.z;
    const float4* __restrict__ inb  = in  + (size_t)b * R * C4;
    float4* __restrict__       outb = out + (size_t)b * CP * R4;

    const int tid   = threadIdx.x;
    const int rtile = blockIdx.x;   // R-tile index (fastest-varying)
    const int ctile = blockIdx.y;   // CP-tile index

    // ---- Load phase: 4x LDG.128 per thread, STS.64 lane-linear ----
    {
        const int tx = tid & 15;                 // float4 col within tile (0..15)
        const int ty = tid >> 4;                 // 0..15
        const int c4 = ctile * (TILE_C / 2) + tx;
        const int r0 = rtile * TILE_R;
#pragma unroll
        for (int k = 0; k < 2; k++) {
            const int m = ty + 16 * k;           // row pair 0..31
            const float4 v0 = inb[(size_t)(r0 + 2 * m    ) * C4 + c4];
            const float4 v1 = inb[(size_t)(r0 + 2 * m + 1) * C4 + c4];
            // logical cols 2tx, 2tx+1 -> storage cols tx, tx+16 (permuted)
            sA[m][tx]      = make_float2(v0.x, v0.y);
            sA[m][tx + 16] = make_float2(v0.z, v0.w);
            sB[m][tx]      = make_float2(v1.x, v1.y);
            sB[m][tx + 16] = make_float2(v1.z, v1.w);
        }
    }

    __syncthreads();

    // ---- Store phase: LDS.64 lane-linear, 4x STG.128 per thread ----
    {
        const int sx = tid & 31;                 // float4 R-index within tile (0..31)
        const int sy = tid >> 5;                 // 0..7
        const int r4 = rtile * (TILE_R / 2) + sx;
#pragma unroll
        for (int n = 0; n < 4; n++) {
            const int c  = sy + 8 * n;           // CP-local col 0..31
            const int sc = (c >> 1) + (c & 1) * 16;   // permuted storage col
            const float2 a  = sA[sx][sc];        // in2[2*sx][c]
            const float2 bb = sB[sx][sc];        // in2[2*sx+1][c]
            outb[(size_t)(ctile * TILE_C + c) * R4 + r4] =
                make_float4(a.x, a.y, bb.x, bb.y);
        }
    }
}

extern "C" void kernel_launch(void* const* d_in, const int* in_sizes, int n_in,
                              void* d_out, int out_size) {
    const float4* in  = (const float4*)d_in[0];
    float4*       out = (float4*)d_out;

    dim3 block(256, 1, 1);
    dim3 grid(R / TILE_R, CP / TILE_C, B);   // (32, 8, 32) = 8192 blocks
    special_flatten_final<<<grid, block>>>(in, out);
}